// round 8
// baseline (speedup 1.0000x reference)
#include <cuda_runtime.h>
#include <math.h>

#define BN 4
#define SN 4096
#define DN 512
#define MTOT (BN * SN)          // 16384
#define HALF_W 128
#define TQ 32
#define SPAN 288                // TQ + 2*HALF_W
#define PS_STRIDE 292           // 4 mod 32 -> conflict-free fragment access

// Scratch (no allocation allowed -> device globals)
__device__ float Qg[MTOT * DN];
__device__ float Kg[MTOT * DN];
__device__ float Vg[MTOT * DN];

// ---------------------------------------------------------------------------
// TF32 helpers
// ---------------------------------------------------------------------------
__device__ __forceinline__ unsigned f2tf(float f) {
    unsigned u;
    asm("cvt.rna.tf32.f32 %0, %1;" : "=r"(u) : "f"(f));
    return u;
}

__device__ __forceinline__ void mma_tf32(float* d, const unsigned* a, const unsigned* b) {
    asm volatile(
        "mma.sync.aligned.m16n8k8.row.col.f32.tf32.tf32.f32 "
        "{%0,%1,%2,%3}, {%4,%5,%6,%7}, {%8,%9}, {%0,%1,%2,%3};"
        : "+f"(d[0]), "+f"(d[1]), "+f"(d[2]), "+f"(d[3])
        : "r"(a[0]), "r"(a[1]), "r"(a[2]), "r"(a[3]),
          "r"(b[0]), "r"(b[1]));
}

// ---------------------------------------------------------------------------
// Kernel 1: QKV projection, TF32 mma, software-pipelined.
// 512 threads (16 warps), block tile 128m x 128n, k-chunk 32.
// Warp grid 4x4; warp tile 32m x 32n (2 m16-frags x 4 n8-frags).
// Register prefetch: chunk kc+1 LDGs issue before chunk kc's mma loop.
// Grid: (128, 12): y -> {Wq,Wk,Wv} x 4 n-blocks.
// ---------------------------------------------------------------------------
#define AS_STRIDE 36
#define BS_STRIDE 136

__global__ __launch_bounds__(512) void qkv_mma(
    const float* __restrict__ x,
    const float* __restrict__ Wq, const float* __restrict__ Wk, const float* __restrict__ Wv,
    const float* __restrict__ bq, const float* __restrict__ bk, const float* __restrict__ bv)
{
    __shared__ unsigned As[128 * AS_STRIDE];   // x tile (tf32 bits) [m][k]
    __shared__ unsigned Bs[32 * BS_STRIDE];    // W tile (tf32 bits) [k][n]

    const int t  = threadIdx.x;
    const int m0 = blockIdx.x * 128;
    const int yb = blockIdx.y;
    const int which = yb >> 2;
    const int n0 = (yb & 3) * 128;

    const float* W    = (which == 0) ? Wq : (which == 1) ? Wk : Wv;
    const float* bias = (which == 0) ? bq : (which == 1) ? bk : bv;
    float*       C    = (which == 0) ? Qg : (which == 1) ? Kg : Vg;

    const int warp = t >> 5, lane = t & 31;
    const int wm = (warp & 3) * 32;
    const int wn = (warp >> 2) * 32;
    const int gid = lane >> 2, tig = lane & 3;

    // Loader coordinates (2 float4 each for A and B per chunk)
    int am[2], ac[2], bk_[2], bc[2];
    #pragma unroll
    for (int i = 0; i < 2; i++) {
        int idx = t + 512 * i;          // 0..1023
        am[i] = idx >> 3;  ac[i] = idx & 7;      // A: 128 rows x 8 float4
        bk_[i] = idx >> 5; bc[i] = idx & 31;     // B: 32 rows x 32 float4
    }

    float d[2][4][4];
    #pragma unroll
    for (int mt = 0; mt < 2; mt++)
        #pragma unroll
        for (int nt = 0; nt < 4; nt++)
            #pragma unroll
            for (int r = 0; r < 4; r++) d[mt][nt][r] = 0.f;

    // Prefetch chunk 0
    float4 pa[2], pb[2];
    #pragma unroll
    for (int i = 0; i < 2; i++) {
        pa[i] = *(const float4*)&x[(m0 + am[i]) * DN + 4 * ac[i]];
        pb[i] = *(const float4*)&W[bk_[i] * DN + n0 + 4 * bc[i]];
    }

    for (int kc = 0; kc < 16; kc++) {
        // Stage prefetched chunk (cvt + vector STS)
        #pragma unroll
        for (int i = 0; i < 2; i++) {
            uint4 ua = make_uint4(f2tf(pa[i].x), f2tf(pa[i].y), f2tf(pa[i].z), f2tf(pa[i].w));
            *(uint4*)&As[am[i] * AS_STRIDE + 4 * ac[i]] = ua;
            uint4 ub = make_uint4(f2tf(pb[i].x), f2tf(pb[i].y), f2tf(pb[i].z), f2tf(pb[i].w));
            *(uint4*)&Bs[bk_[i] * BS_STRIDE + 4 * bc[i]] = ub;
        }
        __syncthreads();

        // Prefetch next chunk (overlaps with the mma loop below)
        if (kc < 15) {
            const int k0 = (kc + 1) * 32;
            #pragma unroll
            for (int i = 0; i < 2; i++) {
                pa[i] = *(const float4*)&x[(m0 + am[i]) * DN + k0 + 4 * ac[i]];
                pb[i] = *(const float4*)&W[(k0 + bk_[i]) * DN + n0 + 4 * bc[i]];
            }
        }

        #pragma unroll
        for (int kt = 0; kt < 4; kt++) {
            unsigned af[2][4], bf[4][2];
            #pragma unroll
            for (int mt = 0; mt < 2; mt++) {
                int r = wm + 16 * mt + gid;
                af[mt][0] = As[r * AS_STRIDE + 8 * kt + tig];
                af[mt][1] = As[(r + 8) * AS_STRIDE + 8 * kt + tig];
                af[mt][2] = As[r * AS_STRIDE + 8 * kt + 4 + tig];
                af[mt][3] = As[(r + 8) * AS_STRIDE + 8 * kt + 4 + tig];
            }
            #pragma unroll
            for (int nt = 0; nt < 4; nt++) {
                int cn = wn + 8 * nt + gid;
                bf[nt][0] = Bs[(8 * kt + tig) * BS_STRIDE + cn];
                bf[nt][1] = Bs[(8 * kt + 4 + tig) * BS_STRIDE + cn];
            }
            #pragma unroll
            for (int mt = 0; mt < 2; mt++)
                #pragma unroll
                for (int nt = 0; nt < 4; nt++)
                    mma_tf32(d[mt][nt], af[mt], bf[nt]);
        }
        __syncthreads();
    }

    // Epilogue: add bias, store
    #pragma unroll
    for (int mt = 0; mt < 2; mt++) {
        int r = m0 + wm + 16 * mt + gid;
        #pragma unroll
        for (int nt = 0; nt < 4; nt++) {
            int cn = n0 + wn + 8 * nt + 2 * tig;
            float b0v = bias[cn], b1v = bias[cn + 1];
            float2 o0 = make_float2(d[mt][nt][0] + b0v, d[mt][nt][1] + b1v);
            float2 o1 = make_float2(d[mt][nt][2] + b0v, d[mt][nt][3] + b1v);
            *(float2*)&C[r * DN + cn]       = o0;
            *(float2*)&C[(r + 8) * DN + cn] = o1;
        }
    }
}

// ---------------------------------------------------------------------------
// Kernel 2: banded attention, all-mma (UNCHANGED from R7 — passed @7.7e-4).
// ---------------------------------------------------------------------------
#define QS_STRIDE 36
#define KS_STRIDE 36
#define VS_STRIDE 264           // 8 mod 32 -> conflict-free b-frag reads
#define ATTN_THREADS 288
#define ATTN_SMEM ((1152 + 288 * KS_STRIDE + TQ * PS_STRIDE) * 4)   // 83456 B

__global__ __launch_bounds__(ATTN_THREADS, 2) void attn_kernel(float* __restrict__ out)
{
    extern __shared__ float sm[];
    float*    Qs  = sm;                               // [32][36]
    float*    Ks  = sm + 1152;                        // [288][36]
    float*    Ps  = sm + 1152 + 288 * KS_STRIDE;      // [32][292]
    unsigned* Qsu = (unsigned*)Qs;
    unsigned* Ksu = (unsigned*)Ks;
    unsigned* Psu = (unsigned*)Ps;
    unsigned* Vsu = (unsigned*)sm;                    // [32][264], phase 3 only

    const int t    = threadIdx.x;
    const int b    = blockIdx.x >> 7;
    const int tile = blockIdx.x & 127;
    const int q0   = tile * TQ;
    const int base = b * SN;
    const int jb0  = q0 - HALF_W;

    const float4* Q4 = (const float4*)Qg;
    const float4* K4 = (const float4*)Kg;
    const float4* V4 = (const float4*)Vg;

    const int warp = t >> 5, lane = t & 31;
    const int gid = lane >> 2, tig = lane & 3;
    const float scale = 0.044194173824159216f;   // 1/sqrt(512)

    // ---- Phase 1: S = Q K^T over 16 k-chunks of 32 dims (TF32 mma)
    float d[2][4][4];
    #pragma unroll
    for (int mt = 0; mt < 2; mt++)
        #pragma unroll
        for (int nf = 0; nf < 4; nf++)
            #pragma unroll
            for (int r = 0; r < 4; r++) d[mt][nf][r] = 0.f;

    for (int kc = 0; kc < 16; kc++) {
        __syncthreads();
        if (t < 256) {
            int q = t >> 3, c = t & 7;
            float4 v = Q4[(base + q0 + q) * 128 + kc * 8 + c];
            unsigned* p = &Qsu[q * QS_STRIDE + 4 * c];
            p[0] = f2tf(v.x * scale); p[1] = f2tf(v.y * scale);
            p[2] = f2tf(v.z * scale); p[3] = f2tf(v.w * scale);
        }
        #pragma unroll
        for (int i = 0; i < 8; i++) {
            int idx = t + ATTN_THREADS * i;     // 0..2303
            int key = idx >> 3, c = idx & 7;
            int j = jb0 + key;
            float4 v = make_float4(0.f, 0.f, 0.f, 0.f);
            if (j >= 0 && j < SN) v = K4[(base + j) * 128 + kc * 8 + c];
            *(float4*)&Ks[key * KS_STRIDE + 4 * c] = v;
        }
        __syncthreads();

        #pragma unroll
        for (int kt = 0; kt < 4; kt++) {
            unsigned af[2][4], bf[4][2];
            #pragma unroll
            for (int mt = 0; mt < 2; mt++) {
                int r = 16 * mt + gid;
                af[mt][0] = Qsu[r * QS_STRIDE + 8 * kt + tig];
                af[mt][1] = Qsu[(r + 8) * QS_STRIDE + 8 * kt + tig];
                af[mt][2] = Qsu[r * QS_STRIDE + 8 * kt + 4 + tig];
                af[mt][3] = Qsu[(r + 8) * QS_STRIDE + 8 * kt + 4 + tig];
            }
            #pragma unroll
            for (int nf = 0; nf < 4; nf++) {
                int key = warp * 32 + 8 * nf + gid;
                bf[nf][0] = Ksu[key * KS_STRIDE + 8 * kt + tig];
                bf[nf][1] = Ksu[key * KS_STRIDE + 8 * kt + 4 + tig];
            }
            #pragma unroll
            for (int mt = 0; mt < 2; mt++)
                #pragma unroll
                for (int nf = 0; nf < 4; nf++)
                    mma_tf32(d[mt][nf], af[mt], bf[nf]);
        }
    }

    #pragma unroll
    for (int mt = 0; mt < 2; mt++)
        #pragma unroll
        for (int nf = 0; nf < 4; nf++) {
            int col = warp * 32 + 8 * nf + 2 * tig;
            int r0 = 16 * mt + gid, r1 = r0 + 8;
            *(float2*)&Ps[r0 * PS_STRIDE + col] = make_float2(d[mt][nf][0], d[mt][nf][1]);
            *(float2*)&Ps[r1 * PS_STRIDE + col] = make_float2(d[mt][nf][2], d[mt][nf][3]);
        }
    __syncthreads();

    // ---- Phase 2: softmax per query row; final probs tf32-rounded (rna)
    for (int row = warp; row < TQ; row += 9) {
        const int lo = row, hi = row + 256;
        float m = -1e30f;
        #pragma unroll
        for (int tt = 0; tt < 9; tt++) {
            int kk = lane + tt * 32;
            int j = jb0 + kk;
            bool valid = (kk >= lo) && (kk <= hi) && (j >= 0) && (j < SN);
            float s = Ps[row * PS_STRIDE + kk];
            if (valid) m = fmaxf(m, s);
        }
        #pragma unroll
        for (int off = 16; off; off >>= 1)
            m = fmaxf(m, __shfl_xor_sync(0xffffffffu, m, off));
        float sum = 0.f;
        float pv[9];
        #pragma unroll
        for (int tt = 0; tt < 9; tt++) {
            int kk = lane + tt * 32;
            int j = jb0 + kk;
            bool valid = (kk >= lo) && (kk <= hi) && (j >= 0) && (j < SN);
            float p = valid ? __expf(Ps[row * PS_STRIDE + kk] - m) : 0.f;
            pv[tt] = p;
            sum += p;
        }
        #pragma unroll
        for (int off = 16; off; off >>= 1)
            sum += __shfl_xor_sync(0xffffffffu, sum, off);
        float inv = 1.f / sum;
        #pragma unroll
        for (int tt = 0; tt < 9; tt++) {
            int kk = lane + tt * 32;
            Psu[row * PS_STRIDE + kk] = f2tf(pv[tt] * inv);
        }
    }

    // ---- Phase 3: O = P @ V via TF32 mma. 2 dim-groups x 9 key chunks.
    for (int dg = 0; dg < 2; dg++) {
        float d3[2][4][4];
        #pragma unroll
        for (int mt = 0; mt < 2; mt++)
            #pragma unroll
            for (int nt = 0; nt < 4; nt++)
                #pragma unroll
                for (int r = 0; r < 4; r++) d3[mt][nt][r] = 0.f;

        for (int c = 0; c < 9; c++) {
            const int jb = jb0 + c * 32;
            __syncthreads();
            #pragma unroll
            for (int i = 0; i < 8; i++) {
                int idx = t + ATTN_THREADS * i;     // 0..2303, need 2048
                if (idx < 2048) {
                    int key = idx >> 6, dq = idx & 63;
                    int j = jb + key;
                    float4 v = make_float4(0.f, 0.f, 0.f, 0.f);
                    if (j >= 0 && j < SN) v = V4[(base + j) * 128 + dg * 64 + dq];
                    unsigned* p = &Vsu[key * VS_STRIDE + 4 * dq];
                    p[0] = f2tf(v.x); p[1] = f2tf(v.y);
                    p[2] = f2tf(v.z); p[3] = f2tf(v.w);
                }
            }
            __syncthreads();

            if (warp < 8) {
                #pragma unroll
                for (int kt = 0; kt < 4; kt++) {
                    unsigned af[2][4], bf[4][2];
                    #pragma unroll
                    for (int mt = 0; mt < 2; mt++) {
                        int r = 16 * mt + gid;
                        int cb = c * 32 + 8 * kt;
                        af[mt][0] = Psu[r * PS_STRIDE + cb + tig];
                        af[mt][1] = Psu[(r + 8) * PS_STRIDE + cb + tig];
                        af[mt][2] = Psu[r * PS_STRIDE + cb + 4 + tig];
                        af[mt][3] = Psu[(r + 8) * PS_STRIDE + cb + 4 + tig];
                    }
                    #pragma unroll
                    for (int nt = 0; nt < 4; nt++) {
                        int cn = warp * 32 + 8 * nt + gid;
                        bf[nt][0] = Vsu[(8 * kt + tig) * VS_STRIDE + cn];
                        bf[nt][1] = Vsu[(8 * kt + 4 + tig) * VS_STRIDE + cn];
                    }
                    #pragma unroll
                    for (int mt = 0; mt < 2; mt++)
                        #pragma unroll
                        for (int nt = 0; nt < 4; nt++)
                            mma_tf32(d3[mt][nt], af[mt], bf[nt]);
                }
            }
        }

        if (warp < 8) {
            #pragma unroll
            for (int mt = 0; mt < 2; mt++) {
                int r0 = q0 + 16 * mt + gid;
                #pragma unroll
                for (int nt = 0; nt < 4; nt++) {
                    int cn = dg * 256 + warp * 32 + 8 * nt + 2 * tig;
                    *(float2*)&out[(base + r0) * DN + cn] =
                        make_float2(d3[mt][nt][0], d3[mt][nt][1]);
                    *(float2*)&out[(base + r0 + 8) * DN + cn] =
                        make_float2(d3[mt][nt][2], d3[mt][nt][3]);
                }
            }
        }
    }
}

// ---------------------------------------------------------------------------
extern "C" void kernel_launch(void* const* d_in, const int* in_sizes, int n_in,
                              void* d_out, int out_size)
{
    const float* x  = (const float*)d_in[0];
    const float* Wq = (const float*)d_in[1];
    const float* bq = (const float*)d_in[2];
    const float* Wk = (const float*)d_in[3];
    const float* bk = (const float*)d_in[4];
    const float* Wv = (const float*)d_in[5];
    const float* bv = (const float*)d_in[6];
    float* out = (float*)d_out;

    cudaFuncSetAttribute(attn_kernel,
                         cudaFuncAttributeMaxDynamicSharedMemorySize, ATTN_SMEM);

    qkv_mma<<<dim3(MTOT / 128, 12), 512>>>(x, Wq, Wk, Wv, bq, bk, bv);
    attn_kernel<<<BN * (SN / TQ), ATTN_THREADS, ATTN_SMEM>>>(out);
}